// round 5
// baseline (speedup 1.0000x reference)
#include <cuda_runtime.h>
#include <math.h>

#define Bb 16
#define LL 2048
#define HID 4096
#define CQ 1536
#define CKV 512
#define HH 32
#define DH 128
#define DR 64
#define HDR (HH*DR)   // 2048
#define HDH (HH*DH)   // 4096
#define L1P (LL+1)    // 2049

#define OFF_CKV (Bb*HID)
#define OFF_KR  (OFF_CKV + Bb*L1P*CKV)

typedef unsigned long long ull;

// ---------------- scratch ----------------
__device__ __align__(16) float g_cQ  [Bb*CQ];
__device__ __align__(16) float g_qC  [Bb*HDH];
__device__ __align__(16) float g_qR  [Bb*HDR];
__device__ __align__(16) float g_kRn [Bb*HDR];
__device__ __align__(16) float g_cKVn[Bb*CKV];
__device__ __align__(16) float g_qCeff[Bb*CKV];
__device__ __align__(16) float g_scores[Bb*L1P];
__device__ __align__(16) float g_probs [Bb*L1P];
__device__ __align__(16) float g_wsum[Bb*CKV];
__device__ __align__(16) float g_v   [Bb*HDH];
__device__ __align__(16) float g_part[4*1024*1024];   // 16 MB split-K partials

// ---------------- f32x2 helpers ----------------
__device__ __forceinline__ void fma2(ull& d, ull a, ull b) {
    asm("fma.rn.f32x2 %0, %1, %2, %0;" : "+l"(d) : "l"(a), "l"(b));
}
__device__ __forceinline__ ull pack2(float lo, float hi) {
    ull r; asm("mov.b64 %0, {%1, %2};" : "=l"(r) : "f"(lo), "f"(hi)); return r;
}
__device__ __forceinline__ void unpack2(ull v, float& lo, float& hi) {
    asm("mov.b64 {%0, %1}, %2;" : "=f"(lo), "=f"(hi) : "l"(v));
}

// ---------------- split-K skinny GEMM: part[y][16][N] = X[16,K_slice] @ W ----------------
// 128 threads, thread -> 4 consecutive cols. Partials STORED (no atomics).
__global__ void __launch_bounds__(128) gemm_xw(
    const float* __restrict__ X, const float* __restrict__ W,
    float* __restrict__ part, int K, int N, int Kper)
{
    __shared__ ull sp[128*8];                 // [k][bpair], Kper <= 128
    int tid = threadIdx.x;
    int kb = blockIdx.y * Kper;

    for (int i = tid; i < Kper*8; i += 128) {
        int k = i >> 3, bp = i & 7;
        sp[i] = pack2(X[(2*bp)*K + kb + k], X[(2*bp+1)*K + kb + k]);
    }
    __syncthreads();

    int n = (blockIdx.x * 128 + tid) * 4;
    if (n >= N) return;

    ull acc[4][8];
#pragma unroll
    for (int c = 0; c < 4; c++)
#pragma unroll
        for (int p = 0; p < 8; p++) acc[c][p] = 0ull;

    const float* Wb = W + (size_t)kb * N + n;
    for (int k0 = 0; k0 < Kper; k0 += 8) {
        float4 w[8];
#pragma unroll
        for (int i = 0; i < 8; i++)
            w[i] = *reinterpret_cast<const float4*>(Wb + (size_t)(k0 + i) * N);
#pragma unroll
        for (int i = 0; i < 8; i++) {
            ull wx = pack2(w[i].x, w[i].x), wy = pack2(w[i].y, w[i].y);
            ull wz = pack2(w[i].z, w[i].z), ww = pack2(w[i].w, w[i].w);
            const ull* xk = &sp[(k0 + i) * 8];
#pragma unroll
            for (int p = 0; p < 8; p++) {
                ull xp = xk[p];
                fma2(acc[0][p], xp, wx);
                fma2(acc[1][p], xp, wy);
                fma2(acc[2][p], xp, wz);
                fma2(acc[3][p], xp, ww);
            }
        }
    }

    float* pp = part + (size_t)blockIdx.y * (16 * N);
#pragma unroll
    for (int p = 0; p < 8; p++) {
        float lo0, hi0, lo1, hi1, lo2, hi2, lo3, hi3;
        unpack2(acc[0][p], lo0, hi0); unpack2(acc[1][p], lo1, hi1);
        unpack2(acc[2][p], lo2, hi2); unpack2(acc[3][p], lo3, hi3);
        float4 r0 = make_float4(lo0, lo1, lo2, lo3);
        float4 r1 = make_float4(hi0, hi1, hi2, hi3);
        *reinterpret_cast<float4*>(pp + (size_t)(2*p)   * N + n) = r0;
        *reinterpret_cast<float4*>(pp + (size_t)(2*p+1) * N + n) = r1;
    }
}

// ---------------- reduce dup slices: dst[i] = sum_d part[d][i] ----------------
__global__ void reduce_part(const float* __restrict__ part, float* __restrict__ dst,
                            int n16, int dup)
{
    int i = blockIdx.x * 256 + threadIdx.x;
    if (i >= n16) return;
    float s0 = 0.f, s1 = 0.f, s2 = 0.f, s3 = 0.f;
    for (int d = 0; d < dup; d += 4) {
        s0 += part[(size_t)(d+0) * n16 + i];
        s1 += part[(size_t)(d+1) * n16 + i];
        s2 += part[(size_t)(d+2) * n16 + i];
        s3 += part[(size_t)(d+3) * n16 + i];
    }
    dst[i] = (s0 + s1) + (s2 + s3);
}

// ---------------- qC_eff[b,n] = dot(qC[b,:4096], W_UK_C[n,:4096]) ----------------
__global__ void qceff_kernel(const float* __restrict__ Wukc) {
    int b = blockIdx.y;
    int wid = threadIdx.x >> 5, lane = threadIdx.x & 31;
    __shared__ float4 sq[HDH / 4];
    for (int i = threadIdx.x; i < HDH / 4; i += blockDim.x)
        sq[i] = reinterpret_cast<const float4*>(g_qC + b * HDH)[i];
    __syncthreads();
    int n = blockIdx.x * 8 + wid;
    const float4* w4 = reinterpret_cast<const float4*>(Wukc + (size_t)n * HDH);
    float sum = 0.f;
#pragma unroll 8
    for (int j = lane; j < HDH / 4; j += 32) {
        float4 a = sq[j], w = w4[j];
        sum += a.x * w.x + a.y * w.y + a.z * w.z + a.w * w.w;
    }
#pragma unroll
    for (int o = 16; o; o >>= 1) sum += __shfl_xor_sync(0xffffffffu, sum, o);
    if (lane == 0) g_qCeff[b * CKV + n] = sum;
}

// ---------------- fused: prefix scores + cache concat/copy ----------------
__global__ void score_copy(const float* __restrict__ cKV, const float* __restrict__ kRc,
                           float* __restrict__ out)
{
    int b = blockIdx.y;
    int wid = threadIdx.x >> 5, lane = threadIdx.x & 31;
    __shared__ float4 sq[(CKV + HDR) / 4];
    for (int i = threadIdx.x; i < CKV / 4; i += blockDim.x)
        sq[i] = reinterpret_cast<const float4*>(g_qCeff + b * CKV)[i];
    for (int i = threadIdx.x; i < HDR / 4; i += blockDim.x)
        sq[CKV / 4 + i] = reinterpret_cast<const float4*>(g_qR + b * HDR)[i];
    __syncthreads();

    int l = blockIdx.x * 8 + wid;
    const float4* c4  = reinterpret_cast<const float4*>(cKV + ((size_t)b * LL + l) * CKV);
    const float4* r4  = reinterpret_cast<const float4*>(kRc + ((size_t)b * LL + l) * HDR);
    float4* oc = reinterpret_cast<float4*>(out + (size_t)OFF_CKV + ((size_t)b * L1P + l) * CKV);
    float4* orr= reinterpret_cast<float4*>(out + (size_t)OFF_KR  + ((size_t)b * L1P + l) * HDR);

    float sum = 0.f;
#pragma unroll
    for (int j = 0; j < (CKV / 4) / 32; j++) {
        int idx = lane + j * 32;
        float4 v = c4[idx]; oc[idx] = v;
        float4 q = sq[idx];
        sum += v.x * q.x + v.y * q.y + v.z * q.z + v.w * q.w;
    }
#pragma unroll
    for (int j = 0; j < (HDR / 4) / 32; j++) {
        int idx = lane + j * 32;
        float4 v = r4[idx]; orr[idx] = v;
        float4 q = sq[CKV / 4 + idx];
        sum += v.x * q.x + v.y * q.y + v.z * q.z + v.w * q.w;
    }
#pragma unroll
    for (int o = 16; o; o >>= 1) sum += __shfl_xor_sync(0xffffffffu, sum, o);
    if (lane == 0) g_scores[b * L1P + l] = sum;
}

// ---------------- fused: new-token score + new cache rows + softmax ----------------
__global__ void softmax_kernel(float* __restrict__ out) {
    int b = blockIdx.x, tid = threadIdx.x;
    __shared__ float red[256];

    // phase 1: new-token score + write new cache rows
    float sum = 0.f;
    for (int i = tid; i < CKV; i += 256) {
        float v = g_cKVn[b * CKV + i];
        out[(size_t)OFF_CKV + ((size_t)b * L1P + LL) * CKV + i] = v;
        sum += v * g_qCeff[b * CKV + i];
    }
    for (int i = tid; i < HDR; i += 256) {
        float v = g_kRn[b * HDR + i];
        out[(size_t)OFF_KR + ((size_t)b * L1P + LL) * HDR + i] = v;
        sum += v * g_qR[b * HDR + i];
    }
    red[tid] = sum; __syncthreads();
    for (int s = 128; s; s >>= 1) { if (tid < s) red[tid] += red[tid + s]; __syncthreads(); }
    if (tid == 0) g_scores[b * L1P + LL] = red[0];
    __syncthreads();

    // phase 2: softmax over 2049
    const float scale = rsqrtf((float)(DH + DR));
    float m = -1e30f;
    for (int i = tid; i < L1P; i += 256) m = fmaxf(m, g_scores[b * L1P + i] * scale);
    red[tid] = m; __syncthreads();
    for (int s = 128; s; s >>= 1) { if (tid < s) red[tid] = fmaxf(red[tid], red[tid + s]); __syncthreads(); }
    m = red[0]; __syncthreads();
    float esum = 0.f;
    for (int i = tid; i < L1P; i += 256) {
        float e = expf(g_scores[b * L1P + i] * scale - m);
        g_probs[b * L1P + i] = e;
        esum += e;
    }
    red[tid] = esum; __syncthreads();
    for (int s = 128; s; s >>= 1) { if (tid < s) red[tid] += red[tid + s]; __syncthreads(); }
    float inv = 1.f / red[0];
    __syncthreads();
    for (int i = tid; i < L1P; i += 256) g_probs[b * L1P + i] *= inv;
}

// ---------------- probs-weighted cKV sum -> partials (no atomics) ----------------
// grid (16 b, 32 l-splits), block 128: thread -> 4 consecutive d
__global__ void wsum_kernel(const float* __restrict__ cKV, float* __restrict__ part) {
    int b = blockIdx.x, ls = blockIdx.y, tid = threadIdx.x;
    const float4* c4 = reinterpret_cast<const float4*>(cKV + (size_t)b * LL * CKV);
    float4 acc = make_float4(0.f, 0.f, 0.f, 0.f);
    int l0 = ls * (LL / 32);
#pragma unroll 8
    for (int l = l0; l < l0 + LL / 32; l++) {
        float p = g_probs[b * L1P + l];
        float4 v = c4[(size_t)l * (CKV / 4) + tid];
        acc.x = fmaf(p, v.x, acc.x); acc.y = fmaf(p, v.y, acc.y);
        acc.z = fmaf(p, v.z, acc.z); acc.w = fmaf(p, v.w, acc.w);
    }
    if (ls == 0) {
        float p = g_probs[b * L1P + LL];
        float4 v = reinterpret_cast<const float4*>(g_cKVn + b * CKV)[tid];
        acc.x = fmaf(p, v.x, acc.x); acc.y = fmaf(p, v.y, acc.y);
        acc.z = fmaf(p, v.z, acc.z); acc.w = fmaf(p, v.w, acc.w);
    }
    // part[ls][b][d]
    *reinterpret_cast<float4*>(part + (size_t)ls * (16 * CKV) + b * CKV + tid * 4) = acc;
}

// ---------------- launch ----------------
extern "C" void kernel_launch(void* const* d_in, const int* in_sizes, int n_in,
                              void* d_out, int out_size) {
    const float* h     = (const float*)d_in[0];
    const float* cKV   = (const float*)d_in[1];
    const float* kRc   = (const float*)d_in[2];
    const float* W_DQ  = (const float*)d_in[3];
    const float* W_DKV = (const float*)d_in[4];
    const float* W_UQC = (const float*)d_in[5];
    const float* W_UQR = (const float*)d_in[6];
    const float* W_KR  = (const float*)d_in[7];
    const float* W_UKC = (const float*)d_in[8];
    const float* W_UVC = (const float*)d_in[9];
    const float* W_O   = (const float*)d_in[10];
    float* out = (float*)d_out;

    float *p_cQ, *p_qC, *p_qR, *p_kRn, *p_cKVn, *p_wsum, *p_v, *p_part;
    cudaGetSymbolAddress((void**)&p_cQ,   g_cQ);
    cudaGetSymbolAddress((void**)&p_qC,   g_qC);
    cudaGetSymbolAddress((void**)&p_qR,   g_qR);
    cudaGetSymbolAddress((void**)&p_kRn,  g_kRn);
    cudaGetSymbolAddress((void**)&p_cKVn, g_cKVn);
    cudaGetSymbolAddress((void**)&p_wsum, g_wsum);
    cudaGetSymbolAddress((void**)&p_v,    g_v);
    cudaGetSymbolAddress((void**)&p_part, g_part);

    // cQ = h @ W_DQ          (K=4096,N=1536): Kper=64, dup=64, grid 3x64
    gemm_xw<<<dim3(3, 64),  128>>>(h, W_DQ, p_part, 4096, 1536, 64);
    reduce_part<<<(16*1536+255)/256, 256>>>(p_part, p_cQ, 16*1536, 64);

    // kR_new = h @ W_KR      (K=4096,N=2048): Kper=64, dup=64, grid 4x64
    gemm_xw<<<dim3(4, 64),  128>>>(h, W_KR, p_part, 4096, 2048, 64);
    reduce_part<<<(16*2048+255)/256, 256>>>(p_part, p_kRn, 16*2048, 64);

    // cKV_new = h @ W_DKV    (K=4096,N=512): Kper=32, dup=128, grid 1x128
    gemm_xw<<<dim3(1, 128), 128>>>(h, W_DKV, p_part, 4096, 512, 32);
    reduce_part<<<(16*512+255)/256, 256>>>(p_part, p_cKVn, 16*512, 128);

    // qC = cQ @ W_UQ_C       (K=1536,N=4096): Kper=48, dup=32, grid 8x32
    gemm_xw<<<dim3(8, 32),  128>>>(p_cQ, W_UQC, p_part, 1536, 4096, 48);
    reduce_part<<<(16*4096+255)/256, 256>>>(p_part, p_qC, 16*4096, 32);

    // qR = cQ @ W_UQ_R       (K=1536,N=2048): Kper=48, dup=32, grid 4x32
    gemm_xw<<<dim3(4, 32),  128>>>(p_cQ, W_UQR, p_part, 1536, 2048, 48);
    reduce_part<<<(16*2048+255)/256, 256>>>(p_part, p_qR, 16*2048, 32);

    // qC_eff = qC @ W_UK_C^T
    qceff_kernel<<<dim3(64, 16), 256>>>(W_UKC);

    // prefix scores + cache copy (HBM-heavy)
    score_copy<<<dim3(256, 16), 256>>>(cKV, kRc, out);

    // new-token score + new cache rows + softmax (fused)
    softmax_kernel<<<16, 256>>>(out);

    // probs-weighted cKV -> partials, then reduce
    wsum_kernel<<<dim3(16, 32), 128>>>(cKV, p_part);
    reduce_part<<<(16*512+255)/256, 256>>>(p_part, p_wsum, 16*512, 32);

    // v = wsum @ W_UV_C      (K=512,N=4096): Kper=32, dup=16, grid 8x16
    gemm_xw<<<dim3(8, 16),  128>>>(p_wsum, W_UVC, p_part, 512, 4096, 32);
    reduce_part<<<(16*4096+255)/256, 256>>>(p_part, p_v, 16*4096, 16);

    // out = v @ W_O          (K=4096,N=4096): Kper=128, dup=32, grid 8x32
    gemm_xw<<<dim3(8, 32),  128>>>(p_v, W_O, p_part, 4096, 4096, 128);
    reduce_part<<<(16*4096+255)/256, 256>>>(p_part, out, 16*4096, 32);
}

// round 6
// speedup vs baseline: 1.1838x; 1.1838x over previous
#include <cuda_runtime.h>
#include <math.h>

#define Bb 16
#define LL 2048
#define HID 4096
#define CQ 1536
#define CKV 512
#define HH 32
#define DH 128
#define DR 64
#define HDR (HH*DR)   // 2048
#define HDH (HH*DH)   // 4096
#define L1P (LL+1)    // 2049

#define OFF_CKV (Bb*HID)
#define OFF_KR  (OFF_CKV + Bb*L1P*CKV)

// comb1 = proj1 output [16][4096] = [cQ(1536) | kRn(2048) | cKVn(512)]
#define C1W   4096
#define C1_KR 1536
#define C1_CKV 3584
// comb2 = proj2 output [16][6144] = [qC(4096) | qR(2048)]
#define C2W   6144
#define C2_QR 4096

typedef unsigned long long ull;

// ---------------- scratch ----------------
__device__ __align__(16) float g_comb1[Bb*C1W];
__device__ __align__(16) float g_comb2[Bb*C2W];
__device__ __align__(16) float g_qCeff[Bb*CKV];
__device__ __align__(16) float g_scores[Bb*L1P];
__device__ __align__(16) float g_probs [Bb*L1P];
__device__ __align__(16) float g_wsum[Bb*CKV];
__device__ __align__(16) float g_v   [Bb*HDH];
__device__ __align__(16) float g_part[4*1024*1024];   // 16 MB split-K partials

// ---------------- f32x2 helpers ----------------
__device__ __forceinline__ void fma2(ull& d, ull a, ull b) {
    asm("fma.rn.f32x2 %0, %1, %2, %0;" : "+l"(d) : "l"(a), "l"(b));
}
__device__ __forceinline__ ull pack2(float lo, float hi) {
    ull r; asm("mov.b64 %0, {%1, %2};" : "=l"(r) : "f"(lo), "f"(hi)); return r;
}
__device__ __forceinline__ void unpack2(ull v, float& lo, float& hi) {
    asm("mov.b64 {%0, %1}, %2;" : "=f"(lo), "=f"(hi) : "l"(v));
}

// ---- multi-weight split-K skinny GEMM: part[y][16][Ntot] = X[16,Kslice] @ [W0|W1|W2] ----
// 128 threads, thread -> 4 consecutive cols (512-col tile, tiles never straddle weights).
__global__ void __launch_bounds__(128) gemm_multi(
    const float* __restrict__ X, int Xs, int K, int Kper,
    const float* __restrict__ W0, int N0,
    const float* __restrict__ W1, int N1,
    const float* __restrict__ W2, int N2,
    float* __restrict__ part)
{
    int Ntot = N0 + N1 + N2;
    __shared__ ull sp[128*8];                 // [k][bpair], Kper <= 128
    int tid = threadIdx.x;
    int kb = blockIdx.y * Kper;

    for (int i = tid; i < Kper*8; i += 128) {
        int k = i >> 3, bp = i & 7;
        sp[i] = pack2(X[(2*bp)*Xs + kb + k], X[(2*bp+1)*Xs + kb + k]);
    }
    __syncthreads();

    int col = blockIdx.x * 512 + tid * 4;
    const float* W; int lc, Ns;
    if (col < N0)           { W = W0; lc = col;           Ns = N0; }
    else if (col < N0 + N1) { W = W1; lc = col - N0;      Ns = N1; }
    else                    { W = W2; lc = col - N0 - N1; Ns = N2; }

    ull acc[4][8];
#pragma unroll
    for (int c = 0; c < 4; c++)
#pragma unroll
        for (int p = 0; p < 8; p++) acc[c][p] = 0ull;

    const float* Wb = W + (size_t)kb * Ns + lc;
    for (int k0 = 0; k0 < Kper; k0 += 8) {
        float4 w[8];
#pragma unroll
        for (int i = 0; i < 8; i++)
            w[i] = *reinterpret_cast<const float4*>(Wb + (size_t)(k0 + i) * Ns);
#pragma unroll
        for (int i = 0; i < 8; i++) {
            ull wx = pack2(w[i].x, w[i].x), wy = pack2(w[i].y, w[i].y);
            ull wz = pack2(w[i].z, w[i].z), ww = pack2(w[i].w, w[i].w);
            const ull* xk = &sp[(k0 + i) * 8];
#pragma unroll
            for (int p = 0; p < 8; p++) {
                ull xp = xk[p];
                fma2(acc[0][p], xp, wx);
                fma2(acc[1][p], xp, wy);
                fma2(acc[2][p], xp, wz);
                fma2(acc[3][p], xp, ww);
            }
        }
    }

    float* pp = part + (size_t)blockIdx.y * (16 * Ntot) + col;
#pragma unroll
    for (int p = 0; p < 8; p++) {
        float lo0, hi0, lo1, hi1, lo2, hi2, lo3, hi3;
        unpack2(acc[0][p], lo0, hi0); unpack2(acc[1][p], lo1, hi1);
        unpack2(acc[2][p], lo2, hi2); unpack2(acc[3][p], lo3, hi3);
        *reinterpret_cast<float4*>(pp + (size_t)(2*p)   * Ntot) = make_float4(lo0, lo1, lo2, lo3);
        *reinterpret_cast<float4*>(pp + (size_t)(2*p+1) * Ntot) = make_float4(hi0, hi1, hi2, hi3);
    }
}

// ---------------- reduce dup slices (float4, MLP=8): dst[i] = sum_d part[d][i] ----------------
__global__ void reduce_part(const float4* __restrict__ part, float4* __restrict__ dst,
                            int n4, int dup)
{
    int i = blockIdx.x * 256 + threadIdx.x;
    if (i >= n4) return;
    float4 acc = make_float4(0.f, 0.f, 0.f, 0.f);
    for (int d0 = 0; d0 < dup; d0 += 8) {
        float4 t[8];
#pragma unroll
        for (int j = 0; j < 8; j++) t[j] = part[(size_t)(d0 + j) * n4 + i];
#pragma unroll
        for (int j = 0; j < 8; j++) {
            acc.x += t[j].x; acc.y += t[j].y; acc.z += t[j].z; acc.w += t[j].w;
        }
    }
    dst[i] = acc;
}

// ---------------- qC_eff[b,n] = dot(qC[b,:4096], W_UK_C[n,:4096]) ----------------
__global__ void qceff_kernel(const float* __restrict__ Wukc, const float* __restrict__ comb2) {
    int b = blockIdx.y;
    int wid = threadIdx.x >> 5, lane = threadIdx.x & 31;
    __shared__ float4 sq[HDH / 4];
    for (int i = threadIdx.x; i < HDH / 4; i += blockDim.x)
        sq[i] = reinterpret_cast<const float4*>(comb2 + (size_t)b * C2W)[i];
    __syncthreads();
    int n = blockIdx.x * 8 + wid;
    const float4* w4 = reinterpret_cast<const float4*>(Wukc + (size_t)n * HDH);
    float sum = 0.f;
#pragma unroll 8
    for (int j = lane; j < HDH / 4; j += 32) {
        float4 a = sq[j], w = w4[j];
        sum += a.x * w.x + a.y * w.y + a.z * w.z + a.w * w.w;
    }
#pragma unroll
    for (int o = 16; o; o >>= 1) sum += __shfl_xor_sync(0xffffffffu, sum, o);
    if (lane == 0) g_qCeff[b * CKV + n] = sum;
}

// ---------------- fused: prefix scores + cache concat/copy ----------------
__global__ void score_copy(const float* __restrict__ cKV, const float* __restrict__ kRc,
                           const float* __restrict__ comb2, float* __restrict__ out)
{
    int b = blockIdx.y;
    int wid = threadIdx.x >> 5, lane = threadIdx.x & 31;
    __shared__ float4 sq[(CKV + HDR) / 4];
    for (int i = threadIdx.x; i < CKV / 4; i += blockDim.x)
        sq[i] = reinterpret_cast<const float4*>(g_qCeff + b * CKV)[i];
    for (int i = threadIdx.x; i < HDR / 4; i += blockDim.x)
        sq[CKV / 4 + i] = reinterpret_cast<const float4*>(comb2 + (size_t)b * C2W + C2_QR)[i];
    __syncthreads();

    int l = blockIdx.x * 8 + wid;
    const float4* c4  = reinterpret_cast<const float4*>(cKV + ((size_t)b * LL + l) * CKV);
    const float4* r4  = reinterpret_cast<const float4*>(kRc + ((size_t)b * LL + l) * HDR);
    float4* oc = reinterpret_cast<float4*>(out + (size_t)OFF_CKV + ((size_t)b * L1P + l) * CKV);
    float4* orr= reinterpret_cast<float4*>(out + (size_t)OFF_KR  + ((size_t)b * L1P + l) * HDR);

    float sum = 0.f;
#pragma unroll
    for (int j = 0; j < (CKV / 4) / 32; j++) {
        int idx = lane + j * 32;
        float4 v = c4[idx]; oc[idx] = v;
        float4 q = sq[idx];
        sum += v.x * q.x + v.y * q.y + v.z * q.z + v.w * q.w;
    }
#pragma unroll
    for (int j = 0; j < (HDR / 4) / 32; j++) {
        int idx = lane + j * 32;
        float4 v = r4[idx]; orr[idx] = v;
        float4 q = sq[CKV / 4 + idx];
        sum += v.x * q.x + v.y * q.y + v.z * q.z + v.w * q.w;
    }
#pragma unroll
    for (int o = 16; o; o >>= 1) sum += __shfl_xor_sync(0xffffffffu, sum, o);
    if (lane == 0) g_scores[b * L1P + l] = sum;
}

// ---------------- fused: new-token score + new cache rows + softmax ----------------
__global__ void softmax_kernel(const float* __restrict__ comb1, float* __restrict__ out) {
    int b = blockIdx.x, tid = threadIdx.x;
    __shared__ float red[256];
    const float* cKVn = comb1 + (size_t)b * C1W + C1_CKV;
    const float* kRn  = comb1 + (size_t)b * C1W + C1_KR;

    float sum = 0.f;
    for (int i = tid; i < CKV; i += 256) {
        float v = cKVn[i];
        out[(size_t)OFF_CKV + ((size_t)b * L1P + LL) * CKV + i] = v;
        sum += v * g_qCeff[b * CKV + i];
    }
    for (int i = tid; i < HDR; i += 256) {
        float v = kRn[i];
        out[(size_t)OFF_KR + ((size_t)b * L1P + LL) * HDR + i] = v;
        sum += v * g_comb2[(size_t)b * C2W + C2_QR + i];
    }
    red[tid] = sum; __syncthreads();
    for (int s = 128; s; s >>= 1) { if (tid < s) red[tid] += red[tid + s]; __syncthreads(); }
    if (tid == 0) g_scores[b * L1P + LL] = red[0];
    __syncthreads();

    const float scale = rsqrtf((float)(DH + DR));
    float m = -1e30f;
    for (int i = tid; i < L1P; i += 256) m = fmaxf(m, g_scores[b * L1P + i] * scale);
    red[tid] = m; __syncthreads();
    for (int s = 128; s; s >>= 1) { if (tid < s) red[tid] = fmaxf(red[tid], red[tid + s]); __syncthreads(); }
    m = red[0]; __syncthreads();
    float esum = 0.f;
    for (int i = tid; i < L1P; i += 256) {
        float e = expf(g_scores[b * L1P + i] * scale - m);
        g_probs[b * L1P + i] = e;
        esum += e;
    }
    red[tid] = esum; __syncthreads();
    for (int s = 128; s; s >>= 1) { if (tid < s) red[tid] += red[tid + s]; __syncthreads(); }
    float inv = 1.f / red[0];
    __syncthreads();
    for (int i = tid; i < L1P; i += 256) g_probs[b * L1P + i] *= inv;
}

// ---------------- probs-weighted cKV sum -> partials ----------------
__global__ void wsum_kernel(const float* __restrict__ cKV, const float* __restrict__ comb1,
                            float* __restrict__ part) {
    int b = blockIdx.x, ls = blockIdx.y, tid = threadIdx.x;
    const float4* c4 = reinterpret_cast<const float4*>(cKV + (size_t)b * LL * CKV);
    float4 acc = make_float4(0.f, 0.f, 0.f, 0.f);
    int l0 = ls * (LL / 32);
#pragma unroll 8
    for (int l = l0; l < l0 + LL / 32; l++) {
        float p = g_probs[b * L1P + l];
        float4 v = c4[(size_t)l * (CKV / 4) + tid];
        acc.x = fmaf(p, v.x, acc.x); acc.y = fmaf(p, v.y, acc.y);
        acc.z = fmaf(p, v.z, acc.z); acc.w = fmaf(p, v.w, acc.w);
    }
    if (ls == 0) {
        float p = g_probs[b * L1P + LL];
        float4 v = *reinterpret_cast<const float4*>(comb1 + (size_t)b * C1W + C1_CKV + tid * 4);
        acc.x = fmaf(p, v.x, acc.x); acc.y = fmaf(p, v.y, acc.y);
        acc.z = fmaf(p, v.z, acc.z); acc.w = fmaf(p, v.w, acc.w);
    }
    *reinterpret_cast<float4*>(part + (size_t)ls * (16 * CKV) + b * CKV + tid * 4) = acc;
}

// ---------------- launch ----------------
extern "C" void kernel_launch(void* const* d_in, const int* in_sizes, int n_in,
                              void* d_out, int out_size) {
    const float* h     = (const float*)d_in[0];
    const float* cKV   = (const float*)d_in[1];
    const float* kRc   = (const float*)d_in[2];
    const float* W_DQ  = (const float*)d_in[3];
    const float* W_DKV = (const float*)d_in[4];
    const float* W_UQC = (const float*)d_in[5];
    const float* W_UQR = (const float*)d_in[6];
    const float* W_KR  = (const float*)d_in[7];
    const float* W_UKC = (const float*)d_in[8];
    const float* W_UVC = (const float*)d_in[9];
    const float* W_O   = (const float*)d_in[10];
    float* out = (float*)d_out;

    float *p_c1, *p_c2, *p_wsum, *p_v, *p_part;
    cudaGetSymbolAddress((void**)&p_c1,   g_comb1);
    cudaGetSymbolAddress((void**)&p_c2,   g_comb2);
    cudaGetSymbolAddress((void**)&p_wsum, g_wsum);
    cudaGetSymbolAddress((void**)&p_v,    g_v);
    cudaGetSymbolAddress((void**)&p_part, g_part);

    // proj1: h @ [W_DQ | W_KR | W_DKV]  (K=4096, Ntot=4096): 8 tiles x dup 64
    gemm_multi<<<dim3(8, 64), 128>>>(h, HID, 4096, 64,
                                     W_DQ, 1536, W_KR, 2048, W_DKV, 512, p_part);
    reduce_part<<<(Bb*C1W/4 + 255)/256, 256>>>((const float4*)p_part, (float4*)p_c1,
                                               Bb*C1W/4, 64);

    // proj2: cQ @ [W_UQ_C | W_UQ_R]  (K=1536, Ntot=6144): 12 tiles x dup 32
    gemm_multi<<<dim3(12, 32), 128>>>(p_c1, C1W, 1536, 48,
                                      W_UQC, 4096, W_UQR, 2048, (const float*)0, 0, p_part);
    reduce_part<<<(Bb*C2W/4 + 255)/256, 256>>>((const float4*)p_part, (float4*)p_c2,
                                               Bb*C2W/4, 32);

    // qC_eff = qC @ W_UK_C^T
    qceff_kernel<<<dim3(64, 16), 256>>>(W_UKC, p_c2);

    // prefix scores + cache copy (HBM-heavy)
    score_copy<<<dim3(256, 16), 256>>>(cKV, kRc, p_c2, out);

    // new-token score + new cache rows + softmax
    softmax_kernel<<<16, 256>>>(p_c1, out);

    // probs-weighted cKV -> partials, then reduce
    wsum_kernel<<<dim3(16, 32), 128>>>(cKV, p_c1, p_part);
    reduce_part<<<(Bb*CKV/4 + 255)/256, 256>>>((const float4*)p_part, (float4*)p_wsum,
                                               Bb*CKV/4, 32);

    // v = wsum @ W_UV_C  (K=512, N=4096): 8 tiles x dup 32, Kper=16
    gemm_multi<<<dim3(8, 32), 128>>>(p_wsum, CKV, 512, 16,
                                     W_UVC, 4096, (const float*)0, 0, (const float*)0, 0, p_part);
    reduce_part<<<(Bb*HDH/4 + 255)/256, 256>>>((const float4*)p_part, (float4*)p_v,
                                               Bb*HDH/4, 32);

    // out = v @ W_O  (K=4096, N=4096): 8 tiles x dup 32, Kper=128
    gemm_multi<<<dim3(8, 32), 128>>>(p_v, HDH, 4096, 128,
                                     W_O, 4096, (const float*)0, 0, (const float*)0, 0, p_part);
    reduce_part<<<(Bb*HDH/4 + 255)/256, 256>>>((const float4*)p_part, (float4*)out,
                                               Bb*HDH/4, 32);
}